// round 13
// baseline (speedup 1.0000x reference)
#include <cuda_runtime.h>
#include <math.h>

#define N0 2048
#define D0 3
#define N1 1024
#define D1 5
#define TS 32
#define PAIR_THREADS 256
#define GRID_PAIR 592               // 148 SMs * 4 resident blocks = whole wave

// dot-product lengths (padded to /4)
#define L0 16      // 9 + 6 + 1 pad
#define L1 40      // 25 + 15
#define P0_REC 32  // L0 * 2 halves (i-pair record)
#define P1_REC 80  // L1 * 2
#define Q0_STR 36  // L0*2 dup + 4 pad  (odd 16B-granule stride)
#define Q1_STR 84  // L1*2 dup + 4 pad  (odd)

// jobs: 528 D5 single tiles (heavy, first) + 1056 D3 double tiles
#define NJOB5 528
#define NJOB  1584
#define SBUF 3968
#define A5_F4 320
#define T5_F4 992
#define A3_F4 128
#define B30_F4 416
#define B31_F4 704

typedef unsigned long long ull;

// Scratch (device globals: allocation-free per harness rules)
__device__ __align__(16) float gP0[(N0 / 2) * P0_REC];
__device__ __align__(16) float gQ0[N0 * Q0_STR];
__device__ __align__(16) float gP1[(N1 / 2) * P1_REC];
__device__ __align__(16) float gQ1[N1 * Q1_STR];
__device__ unsigned g_job[NJOB];
__device__ double g_sum0;
__device__ double g_sum1;
__device__ unsigned int g_done = 0;
__device__ unsigned int g_arrive = 0;
__device__ int g_next;

// ---------------- packed f32x2 helpers (FFMA2: PTX-only) ----------------
__device__ __forceinline__ ull f2dup(float v) {
    ull r;
    asm("mov.b64 %0, {%1, %1};" : "=l"(r) : "f"(v));
    return r;
}
__device__ __forceinline__ void f2unpack(ull v, float& lo, float& hi) {
    asm("mov.b64 {%0, %1}, %2;" : "=f"(lo), "=f"(hi) : "l"(v));
}
__device__ __forceinline__ ull fma2(ull a, ull b, ull c) {
    ull d;
    asm("fma.rn.f32x2 %0, %1, %2, %3;" : "=l"(d) : "l"(a), "l"(b), "l"(c));
    return d;
}
__device__ __forceinline__ ull add2(ull a, ull b) {
    ull d;
    asm("add.rn.f32x2 %0, %1, %2;" : "=l"(d) : "l"(a), "l"(b));
    return d;
}
__device__ __forceinline__ unsigned smem_u32(const void* p) {
    unsigned a;
    asm("{ .reg .u64 t; cvta.to.shared.u64 t, %1; cvt.u32.u64 %0, t; }" : "=r"(a) : "l"(p));
    return a;
}
// L1-cached staging: safe post-barrier (L1 flushed at launch; no pre-barrier
// reads of gP/gQ on this SM, so no stale lines can exist).
__device__ __forceinline__ void cpasync16(unsigned sdst, const void* gsrc) {
    asm volatile("cp.async.ca.shared.global [%0], [%1], 16;" :: "r"(sdst), "l"(gsrc) : "memory");
}

__device__ __forceinline__ void tri_decode(int b, int& ti, int& tj) {
    ti = (int)((sqrtf(8.f * (float)b + 1.f) - 1.f) * 0.5f);
    while ((ti + 1) * (ti + 2) / 2 <= b) ti++;
    while (ti * (ti + 1) / 2 > b) ti--;
    tj = b - ti * (ti + 1) / 2;
}

// ---------------- Phase A: one matrix -> features (p,q vectors) ----------------
__device__ __forceinline__ void prep_matrix0(int i, const float* __restrict__ k0) {
    float a[9];
    float ss = 0.f;
#pragma unroll
    for (int t = 0; t < 9; t++) {
        a[t] = k0[i * 9 + t];
        ss = fmaf(a[t], a[t], ss);
    }
    float rn = 1.f / (sqrtf(ss) + 1e-8f);
#pragma unroll
    for (int t = 0; t < 9; t++) a[t] *= rn;

    float z[L0];
#pragma unroll
    for (int r = 0; r < 3; r++)
#pragma unroll
        for (int k = 0; k < 3; k++)
            z[r * 3 + k] = a[k * 3 + r];
#pragma unroll
    for (int x = 0; x < 3; x++) {
        float h = 0.f;
#pragma unroll
        for (int c = 0; c < 3; c++) h = fmaf(a[x * 3 + c], a[x * 3 + c], h);
        z[9 + x] = h;
    }
    {
        int m = 0;
#pragma unroll
        for (int x = 0; x < 3; x++)
#pragma unroll
            for (int y = x + 1; y < 3; y++) {
                float h = 0.f;
#pragma unroll
                for (int c = 0; c < 3; c++) h = fmaf(a[x * 3 + c], a[y * 3 + c], h);
                z[12 + m] = 2.f * h;
                m++;
            }
    }
    z[15] = 0.f;
    float* qrow = &gQ0[i * Q0_STR];
#pragma unroll
    for (int q = 0; q < L0; q++) {
        qrow[2 * q + 0] = z[q];
        qrow[2 * q + 1] = z[q];
    }
#pragma unroll
    for (int q = 2 * L0; q < Q0_STR; q++) qrow[q] = 0.f;

    float inv[9];
    float c00 = a[4] * a[8] - a[5] * a[7];
    float c10 = a[5] * a[6] - a[3] * a[8];
    float c20 = a[3] * a[7] - a[4] * a[6];
    float det = a[0] * c00 + a[1] * c10 + a[2] * c20;
    float id = 1.f / det;
    inv[0] = c00 * id;
    inv[1] = (a[2] * a[7] - a[1] * a[8]) * id;
    inv[2] = (a[1] * a[5] - a[2] * a[4]) * id;
    inv[3] = c10 * id;
    inv[4] = (a[0] * a[8] - a[2] * a[6]) * id;
    inv[5] = (a[2] * a[3] - a[0] * a[5]) * id;
    inv[6] = c20 * id;
    inv[7] = (a[1] * a[6] - a[0] * a[7]) * id;
    inv[8] = (a[0] * a[4] - a[1] * a[3]) * id;

    float p[L0];
#pragma unroll
    for (int t = 0; t < 9; t++) p[t] = -2.f * inv[t];
#pragma unroll
    for (int x = 0; x < 3; x++) {
        float g = 0.f;
#pragma unroll
        for (int r = 0; r < 3; r++) g = fmaf(inv[r * 3 + x], inv[r * 3 + x], g);
        p[9 + x] = g;
    }
    {
        int m = 0;
#pragma unroll
        for (int x = 0; x < 3; x++)
#pragma unroll
            for (int y = x + 1; y < 3; y++) {
                float g = 0.f;
#pragma unroll
                for (int r = 0; r < 3; r++) g = fmaf(inv[r * 3 + x], inv[r * 3 + y], g);
                p[12 + m] = g;
                m++;
            }
    }
    p[15] = 0.f;
    int pair = i >> 1, h = i & 1;
    float* rec = &gP0[pair * P0_REC];
#pragma unroll
    for (int q = 0; q < L0; q++) rec[2 * q + h] = p[q];
}

__device__ __forceinline__ void prep_matrix1(int i, const float* __restrict__ k1) {
    float a[5][5];
    float ss = 0.f;
#pragma unroll
    for (int r = 0; r < 5; r++)
#pragma unroll
        for (int c = 0; c < 5; c++) {
            float v = k1[i * 25 + r * 5 + c];
            a[r][c] = v;
            ss = fmaf(v, v, ss);
        }
    float rn = 1.f / (sqrtf(ss) + 1e-8f);
#pragma unroll
    for (int r = 0; r < 5; r++)
#pragma unroll
        for (int c = 0; c < 5; c++) a[r][c] *= rn;

    // q vector first (z dead before inversion -> lower register peak)
    {
        float z[L1];
#pragma unroll
        for (int r = 0; r < 5; r++)
#pragma unroll
            for (int k = 0; k < 5; k++)
                z[r * 5 + k] = a[k][r];
#pragma unroll
        for (int x = 0; x < 5; x++) {
            float h = 0.f;
#pragma unroll
            for (int c = 0; c < 5; c++) h = fmaf(a[x][c], a[x][c], h);
            z[25 + x] = h;
        }
        int m = 0;
#pragma unroll
        for (int x = 0; x < 5; x++)
#pragma unroll
            for (int y = x + 1; y < 5; y++) {
                float h = 0.f;
#pragma unroll
                for (int c = 0; c < 5; c++) h = fmaf(a[x][c], a[y][c], h);
                z[30 + m] = 2.f * h;
                m++;
            }
        float* qrow = &gQ1[i * Q1_STR];
#pragma unroll
        for (int q = 0; q < L1; q++) {
            qrow[2 * q + 0] = z[q];
            qrow[2 * q + 1] = z[q];
        }
#pragma unroll
        for (int q = 2 * L1; q < Q1_STR; q++) qrow[q] = 0.f;
    }

    float b[5][5];
#pragma unroll
    for (int r = 0; r < 5; r++)
#pragma unroll
        for (int c = 0; c < 5; c++) b[r][c] = (r == c) ? 1.f : 0.f;
#pragma unroll
    for (int col = 0; col < 5; col++) {
#pragma unroll
        for (int r = col + 1; r < 5; r++) {
            bool sw = fabsf(a[r][col]) > fabsf(a[col][col]);
#pragma unroll
            for (int c = 0; c < 5; c++) {
                float t0 = a[col][c], t1 = a[r][c];
                a[col][c] = sw ? t1 : t0;
                a[r][c]   = sw ? t0 : t1;
                float u0 = b[col][c], u1 = b[r][c];
                b[col][c] = sw ? u1 : u0;
                b[r][c]   = sw ? u0 : u1;
            }
        }
        float piv = 1.f / a[col][col];
#pragma unroll
        for (int c = 0; c < 5; c++) {
            a[col][c] *= piv;
            b[col][c] *= piv;
        }
#pragma unroll
        for (int r = 0; r < 5; r++) {
            if (r == col) continue;
            float f = a[r][col];
#pragma unroll
            for (int c = 0; c < 5; c++) {
                a[r][c] = fmaf(-f, a[col][c], a[r][c]);
                b[r][c] = fmaf(-f, b[col][c], b[r][c]);
            }
        }
    }

    int pair = i >> 1, h = i & 1;
    float* rec = &gP1[pair * P1_REC];
#pragma unroll
    for (int r = 0; r < 5; r++)
#pragma unroll
        for (int k = 0; k < 5; k++)
            rec[2 * (r * 5 + k) + h] = -2.f * b[r][k];
#pragma unroll
    for (int x = 0; x < 5; x++) {
        float g = 0.f;
#pragma unroll
        for (int r = 0; r < 5; r++) g = fmaf(b[r][x], b[r][x], g);
        rec[2 * (25 + x) + h] = g;
    }
    {
        int m = 0;
#pragma unroll
        for (int x = 0; x < 5; x++)
#pragma unroll
            for (int y = x + 1; y < 5; y++) {
                float g = 0.f;
#pragma unroll
                for (int r = 0; r < 5; r++) g = fmaf(b[r][x], b[r][y], g);
                rec[2 * (30 + m) + h] = g;
                m++;
            }
    }
}

// ---------------- cp.async staging of one job into a smem buffer ----------------
__device__ __forceinline__ void issue_copies(unsigned jd, float* sdst, int t) {
    unsigned sa = smem_u32(sdst);
    int ti = (jd >> 8) & 255;
    if (jd & 0x80000000u) {  // D5 single tile
        int tj = jd & 255;
        const float4* A = ((const float4*)gP1) + ti * (16 * P1_REC / 4);
        const float4* B = ((const float4*)gQ1) + tj * (TS * Q1_STR / 4);
#pragma unroll
        for (int k = 0; k < 4; k++) {
            int idx = t + k * PAIR_THREADS;
            if (idx < A5_F4) cpasync16(sa + idx * 16, A + idx);
            else if (idx < T5_F4) cpasync16(sa + idx * 16, B + (idx - A5_F4));
        }
    } else {                 // D3 double tile
        int tjp = jd & 255;
        int tj0 = 2 * tjp;
        bool two = (tj0 + 1 <= ti);
        const float4* A = ((const float4*)gP0) + ti * (16 * P0_REC / 4);
        const float4* B0 = ((const float4*)gQ0) + tj0 * (TS * Q0_STR / 4);
#pragma unroll
        for (int k = 0; k < 3; k++) {
            int idx = t + k * PAIR_THREADS;
            if (idx < A3_F4) cpasync16(sa + idx * 16, A + idx);
            else if (idx < B30_F4) cpasync16(sa + idx * 16, B0 + (idx - A3_F4));
            else if (idx < B31_F4 && two) cpasync16(sa + idx * 16, B0 + (idx - A3_F4));
        }
    }
}

// ---------------- epilogue for one packed s-pair ----------------
__device__ __forceinline__ void finish(ull s, int ibase, int j, bool diag, float& val) {
    float lo, hi;
    f2unpack(s, lo, hi);
    lo = fmaxf(lo, 0.f);
    hi = fmaxf(hi, 0.f);
    if ((!diag || ibase > j) && lo < 1.f) val += 1.f - sqrtf(lo);
    if ((!diag || ibase + 1 > j) && hi < 1.f) val += 1.f - sqrtf(hi);
}

// ---------------- compute: D5 single tile ----------------
__device__ __forceinline__ void compute5(unsigned jd, const float* s, int t, float& val) {
    const int ti = (jd >> 8) & 255, tj = jd & 255;
    const int w = t >> 5, l = t & 31;
    const int j = tj * TS + l;
    const bool diag = (ti == tj);
    const ulonglong2* Ap0 = (const ulonglong2*)(s + (2 * w) * P1_REC);
    const ulonglong2* Ap1 = (const ulonglong2*)(s + (2 * w + 1) * P1_REC);
    const ulonglong2* Zp  = (const ulonglong2*)(s + 4 * A5_F4 + l * Q1_STR);

    ull xa = f2dup((float)D1), xb = 0ULL, ya = f2dup((float)D1), yb = 0ULL;
#pragma unroll
    for (int qq = 0; qq < L1 / 2; qq++) {
        ulonglong2 z = Zp[qq];
        ulonglong2 a0 = Ap0[qq];
        ulonglong2 a1 = Ap1[qq];
        xa = fma2(a0.x, z.x, xa);
        xb = fma2(a0.y, z.y, xb);
        ya = fma2(a1.x, z.x, ya);
        yb = fma2(a1.y, z.y, yb);
    }
    const int ib = ti * TS + 4 * w;
    finish(add2(xa, xb), ib, j, diag, val);
    finish(add2(ya, yb), ib + 2, j, diag, val);
}

// ---------------- compute: D3 double tile (A loads shared in registers) ----------------
__device__ __forceinline__ void compute3x2(unsigned jd, const float* s, int t, float& val) {
    const int ti = (jd >> 8) & 255, tjp = jd & 255;
    const int tj0 = 2 * tjp;
    const bool two = (tj0 + 1 <= ti);
    const int w = t >> 5, l = t & 31;
    const ulonglong2* Ap0 = (const ulonglong2*)(s + (2 * w) * P0_REC);
    const ulonglong2* Ap1 = (const ulonglong2*)(s + (2 * w + 1) * P0_REC);
    const ulonglong2* Z0  = (const ulonglong2*)(s + 4 * A3_F4 + l * Q0_STR);
    const ulonglong2* Z1  = (const ulonglong2*)(s + 4 * A3_F4 + TS * Q0_STR + l * Q0_STR);

    ull x0a = f2dup((float)D0), x0b = 0ULL, y0a = f2dup((float)D0), y0b = 0ULL;
    ull x1a = x0a, x1b = 0ULL, y1a = x0a, y1b = 0ULL;
    if (two) {
#pragma unroll
        for (int qq = 0; qq < L0 / 2; qq++) {
            ulonglong2 a0 = Ap0[qq];
            ulonglong2 a1 = Ap1[qq];
            ulonglong2 z0 = Z0[qq];
            ulonglong2 z1 = Z1[qq];
            x0a = fma2(a0.x, z0.x, x0a);
            x0b = fma2(a0.y, z0.y, x0b);
            y0a = fma2(a1.x, z0.x, y0a);
            y0b = fma2(a1.y, z0.y, y0b);
            x1a = fma2(a0.x, z1.x, x1a);
            x1b = fma2(a0.y, z1.y, x1b);
            y1a = fma2(a1.x, z1.x, y1a);
            y1b = fma2(a1.y, z1.y, y1b);
        }
    } else {
#pragma unroll
        for (int qq = 0; qq < L0 / 2; qq++) {
            ulonglong2 a0 = Ap0[qq];
            ulonglong2 a1 = Ap1[qq];
            ulonglong2 z0 = Z0[qq];
            x0a = fma2(a0.x, z0.x, x0a);
            x0b = fma2(a0.y, z0.y, x0b);
            y0a = fma2(a1.x, z0.x, y0a);
            y0b = fma2(a1.y, z0.y, y0b);
        }
    }
    const int ib = ti * TS + 4 * w;
    {
        const int j = tj0 * TS + l;
        const bool diag = (ti == tj0);
        finish(add2(x0a, x0b), ib, j, diag, val);
        finish(add2(y0a, y0b), ib + 2, j, diag, val);
    }
    if (two) {
        const int j = (tj0 + 1) * TS + l;
        const bool diag = (ti == tj0 + 1);
        finish(add2(x1a, x1b), ib, j, diag, val);
        finish(add2(y1a, y1b), ib + 2, j, diag, val);
    }
}

// ---------------- Single fused persistent kernel ----------------
__global__ void __launch_bounds__(PAIR_THREADS, 4) fused_kernel(
    float* __restrict__ out, const float* __restrict__ k0, const float* __restrict__ k1) {
    __shared__ __align__(16) float sbuf[2][SBUF];
    __shared__ float warp_sums[2][PAIR_THREADS / 32];
    __shared__ int s_next;

    const int t = threadIdx.x;
    const int b = blockIdx.x;
    const int w = t >> 5;
    const int l = t & 31;

    // ======== Phase A: prep, one matrix per WARP (8 GJ latencies overlap/block) ========
    {
        if (b == 0 && t == 0) {
            g_sum0 = 0.0;
            g_sum1 = 0.0;
            g_next = GRID_PAIR;
        }
        // matrices: m = b*8 + w, lane 0 of each warp computes one matrix
        if (l == 0) {
            int m = b * 8 + w;
            if (m < N0) prep_matrix0(m, k0);
            else if (m < N0 + N1) prep_matrix1(m - N0, k1);
        }
        // job table: jid = b*3 + t for t<3
        if (t < 3) {
            int jid = b * 3 + t;
            if (jid < NJOB) {
                if (jid < NJOB5) {
                    int ti, tj;
                    tri_decode(jid, ti, tj);
                    g_job[jid] = 0x80000000u | ((unsigned)ti << 8) | (unsigned)tj;
                } else {
                    int jj = jid - NJOB5;
                    int ti = 0, acc = 0;
                    while (acc + (ti / 2 + 1) <= jj) { acc += ti / 2 + 1; ti++; }
                    g_job[jid] = ((unsigned)ti << 8) | (unsigned)(jj - acc);
                }
            }
        }
        __syncthreads();
        // grid-wide barrier (all 592 blocks resident: grid == one full wave)
        if (t == 0) {
            __threadfence();
            atomicAdd(&g_arrive, 1u);
            while (*(volatile unsigned int*)&g_arrive < GRID_PAIR) {}
        }
        __syncthreads();
    }

    // ======== Phase B: pairwise loss (R11 pipeline, verbatim) ========
    float val0 = 0.f, val1 = 0.f;

    unsigned jd_curr = __ldcg(&g_job[b]);
    issue_copies(jd_curr, sbuf[0], t);
    asm volatile("cp.async.commit_group;" ::: "memory");
    if (t == 0) s_next = atomicAdd(&g_next, 1);
    asm volatile("cp.async.wait_group 0;" ::: "memory");
    __syncthreads();
    int nxt = s_next;
    int buf = 0;

    while (true) {
        unsigned jd_next = 0;
        if (nxt < NJOB) {
            jd_next = __ldcg(&g_job[nxt]);
            issue_copies(jd_next, sbuf[buf ^ 1], t);
            if (t == 0) s_next = atomicAdd(&g_next, 1);
        }
        asm volatile("cp.async.commit_group;" ::: "memory");
        if (jd_curr & 0x80000000u) compute5(jd_curr, sbuf[buf], t, val1);
        else                       compute3x2(jd_curr, sbuf[buf], t, val0);
        if (nxt >= NJOB) break;
        asm volatile("cp.async.wait_group 0;" ::: "memory");
        __syncthreads();
        jd_curr = jd_next;
        nxt = s_next;
        buf ^= 1;
    }

    // block reduction of both accumulators
#pragma unroll
    for (int off = 16; off > 0; off >>= 1) {
        val0 += __shfl_down_sync(0xFFFFFFFFu, val0, off);
        val1 += __shfl_down_sync(0xFFFFFFFFu, val1, off);
    }
    if (l == 0) {
        warp_sums[0][w] = val0;
        warp_sums[1][w] = val1;
    }
    __syncthreads();
    if (t == 0) {
        float b0 = 0.f, b1 = 0.f;
#pragma unroll
        for (int ww = 0; ww < PAIR_THREADS / 32; ww++) {
            b0 += warp_sums[0][ww];
            b1 += warp_sums[1][ww];
        }
        if (b0 != 0.f) atomicAdd(&g_sum0, (double)b0);
        if (b1 != 0.f) atomicAdd(&g_sum1, (double)b1);
        __threadfence();
        unsigned int done = atomicAdd(&g_done, 1u);
        if (done == GRID_PAIR - 1) {
            __threadfence();
            double s0 = *(volatile double*)&g_sum0;
            double s1 = *(volatile double*)&g_sum1;
            double l0 = 2.0 * s0 / ((double)N0 * (double)(N0 - 1));
            double l1 = 2.0 * s1 / ((double)N1 * (double)(N1 - 1));
            out[0] = (float)(0.5 * (l0 + l1));
            g_done = 0;    // reset for next graph replay
            g_arrive = 0;  // reset phase-A barrier
        }
    }
}

extern "C" void kernel_launch(void* const* d_in, const int* in_sizes, int n_in,
                              void* d_out, int out_size) {
    const float* k0 = (const float*)d_in[0];
    const float* k1 = (const float*)d_in[1];
    float* out = (float*)d_out;

    fused_kernel<<<GRID_PAIR, PAIR_THREADS>>>(out, k0, k1);
}

// round 14
// speedup vs baseline: 1.4238x; 1.4238x over previous
#include <cuda_runtime.h>
#include <math.h>

#define N0 2048
#define D0 3
#define N1 1024
#define D1 5
#define TS 32
#define PAIR_THREADS 256
#define GRID_PAIR 592               // 148 SMs * 4 resident blocks = whole wave

// dot-product lengths (padded to /4)
#define L0 16      // 9 + 6 + 1 pad
#define L1 40      // 25 + 15
#define P0_REC 32  // L0 * 2 halves (i-pair record)
#define P1_REC 80  // L1 * 2
#define Q0_STR 36  // L0*2 dup + 4 pad  (odd 16B-granule stride)
#define Q1_STR 84  // L1*2 dup + 4 pad  (odd)

// jobs: 528 D5 single tiles (heavy, first) + 1056 D3 double tiles
#define NJOB5 528
#define NJOB  1584
#define SBUF 3968
#define A5_F4 320
#define T5_F4 992
#define A3_F4 128
#define B30_F4 416
#define B31_F4 704

typedef unsigned long long ull;

// Scratch (device globals: allocation-free per harness rules)
__device__ __align__(16) float gP0[(N0 / 2) * P0_REC];
__device__ __align__(16) float gQ0[N0 * Q0_STR];
__device__ __align__(16) float gP1[(N1 / 2) * P1_REC];
__device__ __align__(16) float gQ1[N1 * Q1_STR];
__device__ unsigned g_job[NJOB];
__device__ double g_sum0;
__device__ double g_sum1;
__device__ unsigned int g_done = 0;
__device__ unsigned int g_arrive = 0;
__device__ int g_next;

// ---------------- packed f32x2 helpers (FFMA2: PTX-only) ----------------
__device__ __forceinline__ ull f2dup(float v) {
    ull r;
    asm("mov.b64 %0, {%1, %1};" : "=l"(r) : "f"(v));
    return r;
}
__device__ __forceinline__ void f2unpack(ull v, float& lo, float& hi) {
    asm("mov.b64 {%0, %1}, %2;" : "=f"(lo), "=f"(hi) : "l"(v));
}
__device__ __forceinline__ ull fma2(ull a, ull b, ull c) {
    ull d;
    asm("fma.rn.f32x2 %0, %1, %2, %3;" : "=l"(d) : "l"(a), "l"(b), "l"(c));
    return d;
}
__device__ __forceinline__ ull add2(ull a, ull b) {
    ull d;
    asm("add.rn.f32x2 %0, %1, %2;" : "=l"(d) : "l"(a), "l"(b));
    return d;
}
__device__ __forceinline__ unsigned smem_u32(const void* p) {
    unsigned a;
    asm("{ .reg .u64 t; cvta.to.shared.u64 t, %1; cvt.u32.u64 %0, t; }" : "=r"(a) : "l"(p));
    return a;
}
// L1-cached staging: safe post-barrier (L1 flushed at launch; this SM's phase-A
// stores are no-allocate, so no stale gP/gQ lines can exist in local L1).
__device__ __forceinline__ void cpasync16(unsigned sdst, const void* gsrc) {
    asm volatile("cp.async.ca.shared.global [%0], [%1], 16;" :: "r"(sdst), "l"(gsrc) : "memory");
}

__device__ __forceinline__ void tri_decode(int b, int& ti, int& tj) {
    ti = (int)((sqrtf(8.f * (float)b + 1.f) - 1.f) * 0.5f);
    while ((ti + 1) * (ti + 2) / 2 <= b) ti++;
    while (ti * (ti + 1) / 2 > b) ti--;
    tj = b - ti * (ti + 1) / 2;
}

// ---------------- Phase A half-tasks (register-lean, streaming writes) ----------------

// D0: full task (p+q), peak regs ~35
__device__ __forceinline__ void prep0_all(int i, const float* __restrict__ k0) {
    float a[9];
    float ss = 0.f;
#pragma unroll
    for (int t = 0; t < 9; t++) {
        a[t] = k0[i * 9 + t];
        ss = fmaf(a[t], a[t], ss);
    }
    float rn = 1.f / (sqrtf(ss) + 1e-8f);
#pragma unroll
    for (int t = 0; t < 9; t++) a[t] *= rn;

    // q features -> gQ0 (duplicated), streamed
    float* qrow = &gQ0[i * Q0_STR];
#pragma unroll
    for (int r = 0; r < 3; r++)
#pragma unroll
        for (int k = 0; k < 3; k++) {
            float v = a[k * 3 + r];
            qrow[2 * (r * 3 + k) + 0] = v;
            qrow[2 * (r * 3 + k) + 1] = v;
        }
#pragma unroll
    for (int x = 0; x < 3; x++) {
        float h = 0.f;
#pragma unroll
        for (int c = 0; c < 3; c++) h = fmaf(a[x * 3 + c], a[x * 3 + c], h);
        qrow[2 * (9 + x) + 0] = h;
        qrow[2 * (9 + x) + 1] = h;
    }
    {
        int m = 0;
#pragma unroll
        for (int x = 0; x < 3; x++)
#pragma unroll
            for (int y = x + 1; y < 3; y++) {
                float h = 0.f;
#pragma unroll
                for (int c = 0; c < 3; c++) h = fmaf(a[x * 3 + c], a[y * 3 + c], h);
                qrow[2 * (12 + m) + 0] = 2.f * h;
                qrow[2 * (12 + m) + 1] = 2.f * h;
                m++;
            }
    }
#pragma unroll
    for (int q = 2 * 15; q < Q0_STR; q++) qrow[q] = 0.f;

    // inverse (adjugate) + p features -> gP0 (pair-interleaved), streamed
    float inv[9];
    float c00 = a[4] * a[8] - a[5] * a[7];
    float c10 = a[5] * a[6] - a[3] * a[8];
    float c20 = a[3] * a[7] - a[4] * a[6];
    float det = a[0] * c00 + a[1] * c10 + a[2] * c20;
    float id = 1.f / det;
    inv[0] = c00 * id;
    inv[1] = (a[2] * a[7] - a[1] * a[8]) * id;
    inv[2] = (a[1] * a[5] - a[2] * a[4]) * id;
    inv[3] = c10 * id;
    inv[4] = (a[0] * a[8] - a[2] * a[6]) * id;
    inv[5] = (a[2] * a[3] - a[0] * a[5]) * id;
    inv[6] = c20 * id;
    inv[7] = (a[1] * a[6] - a[0] * a[7]) * id;
    inv[8] = (a[0] * a[4] - a[1] * a[3]) * id;

    int pair = i >> 1, h = i & 1;
    float* rec = &gP0[pair * P0_REC];
#pragma unroll
    for (int t = 0; t < 9; t++) rec[2 * t + h] = -2.f * inv[t];
#pragma unroll
    for (int x = 0; x < 3; x++) {
        float g = 0.f;
#pragma unroll
        for (int r = 0; r < 3; r++) g = fmaf(inv[r * 3 + x], inv[r * 3 + x], g);
        rec[2 * (9 + x) + h] = g;
    }
    {
        int m = 0;
#pragma unroll
        for (int x = 0; x < 3; x++)
#pragma unroll
            for (int y = x + 1; y < 3; y++) {
                float g = 0.f;
#pragma unroll
                for (int r = 0; r < 3; r++) g = fmaf(inv[r * 3 + x], inv[r * 3 + y], g);
                rec[2 * (12 + m) + h] = g;
                m++;
            }
    }
    rec[2 * 15 + h] = 0.f;
}

// D5 q-side: normalize + stream z features. Peak regs ~ a[25]+temps.
__device__ __forceinline__ void prep5_q(int i, const float* __restrict__ k1) {
    float a[5][5];
    float ss = 0.f;
#pragma unroll
    for (int r = 0; r < 5; r++)
#pragma unroll
        for (int c = 0; c < 5; c++) {
            float v = k1[i * 25 + r * 5 + c];
            a[r][c] = v;
            ss = fmaf(v, v, ss);
        }
    float rn = 1.f / (sqrtf(ss) + 1e-8f);
#pragma unroll
    for (int r = 0; r < 5; r++)
#pragma unroll
        for (int c = 0; c < 5; c++) a[r][c] *= rn;

    float* qrow = &gQ1[i * Q1_STR];
#pragma unroll
    for (int r = 0; r < 5; r++)
#pragma unroll
        for (int k = 0; k < 5; k++) {
            float v = a[k][r];
            qrow[2 * (r * 5 + k) + 0] = v;
            qrow[2 * (r * 5 + k) + 1] = v;
        }
#pragma unroll
    for (int x = 0; x < 5; x++) {
        float h = 0.f;
#pragma unroll
        for (int c = 0; c < 5; c++) h = fmaf(a[x][c], a[x][c], h);
        qrow[2 * (25 + x) + 0] = h;
        qrow[2 * (25 + x) + 1] = h;
    }
    {
        int m = 0;
#pragma unroll
        for (int x = 0; x < 5; x++)
#pragma unroll
            for (int y = x + 1; y < 5; y++) {
                float h = 0.f;
#pragma unroll
                for (int c = 0; c < 5; c++) h = fmaf(a[x][c], a[y][c], h);
                qrow[2 * (30 + m) + 0] = 2.f * h;
                qrow[2 * (30 + m) + 1] = 2.f * h;
                m++;
            }
    }
#pragma unroll
    for (int q = 2 * L1; q < Q1_STR; q++) qrow[q] = 0.f;
}

// D5 p-side: normalize + Gauss-Jordan + stream p features. Peak regs ~ a+b = 50.
__device__ __forceinline__ void prep5_p(int i, const float* __restrict__ k1) {
    float a[5][5], bm[5][5];
    float ss = 0.f;
#pragma unroll
    for (int r = 0; r < 5; r++)
#pragma unroll
        for (int c = 0; c < 5; c++) {
            float v = k1[i * 25 + r * 5 + c];
            a[r][c] = v;
            ss = fmaf(v, v, ss);
        }
    float rn = 1.f / (sqrtf(ss) + 1e-8f);
#pragma unroll
    for (int r = 0; r < 5; r++)
#pragma unroll
        for (int c = 0; c < 5; c++) {
            a[r][c] *= rn;
            bm[r][c] = (r == c) ? 1.f : 0.f;
        }
#pragma unroll
    for (int col = 0; col < 5; col++) {
#pragma unroll
        for (int r = col + 1; r < 5; r++) {
            bool sw = fabsf(a[r][col]) > fabsf(a[col][col]);
#pragma unroll
            for (int c = 0; c < 5; c++) {
                float t0 = a[col][c], t1 = a[r][c];
                a[col][c] = sw ? t1 : t0;
                a[r][c]   = sw ? t0 : t1;
                float u0 = bm[col][c], u1 = bm[r][c];
                bm[col][c] = sw ? u1 : u0;
                bm[r][c]   = sw ? u0 : u1;
            }
        }
        float piv = 1.f / a[col][col];
#pragma unroll
        for (int c = 0; c < 5; c++) {
            a[col][c] *= piv;
            bm[col][c] *= piv;
        }
#pragma unroll
        for (int r = 0; r < 5; r++) {
            if (r == col) continue;
            float f = a[r][col];
#pragma unroll
            for (int c = 0; c < 5; c++) {
                a[r][c] = fmaf(-f, a[col][c], a[r][c]);
                bm[r][c] = fmaf(-f, bm[col][c], bm[r][c]);
            }
        }
    }

    int pair = i >> 1, h = i & 1;
    float* rec = &gP1[pair * P1_REC];
#pragma unroll
    for (int r = 0; r < 5; r++)
#pragma unroll
        for (int k = 0; k < 5; k++)
            rec[2 * (r * 5 + k) + h] = -2.f * bm[r][k];
#pragma unroll
    for (int x = 0; x < 5; x++) {
        float g = 0.f;
#pragma unroll
        for (int r = 0; r < 5; r++) g = fmaf(bm[r][x], bm[r][x], g);
        rec[2 * (25 + x) + h] = g;
    }
    {
        int m = 0;
#pragma unroll
        for (int x = 0; x < 5; x++)
#pragma unroll
            for (int y = x + 1; y < 5; y++) {
                float g = 0.f;
#pragma unroll
                for (int r = 0; r < 5; r++) g = fmaf(bm[r][x], bm[r][y], g);
                rec[2 * (30 + m) + h] = g;
                m++;
            }
    }
}

// ---------------- cp.async staging of one job into a smem buffer ----------------
__device__ __forceinline__ void issue_copies(unsigned jd, float* sdst, int t) {
    unsigned sa = smem_u32(sdst);
    int ti = (jd >> 8) & 255;
    if (jd & 0x80000000u) {  // D5 single tile
        int tj = jd & 255;
        const float4* A = ((const float4*)gP1) + ti * (16 * P1_REC / 4);
        const float4* B = ((const float4*)gQ1) + tj * (TS * Q1_STR / 4);
#pragma unroll
        for (int k = 0; k < 4; k++) {
            int idx = t + k * PAIR_THREADS;
            if (idx < A5_F4) cpasync16(sa + idx * 16, A + idx);
            else if (idx < T5_F4) cpasync16(sa + idx * 16, B + (idx - A5_F4));
        }
    } else {                 // D3 double tile
        int tjp = jd & 255;
        int tj0 = 2 * tjp;
        bool two = (tj0 + 1 <= ti);
        const float4* A = ((const float4*)gP0) + ti * (16 * P0_REC / 4);
        const float4* B0 = ((const float4*)gQ0) + tj0 * (TS * Q0_STR / 4);
#pragma unroll
        for (int k = 0; k < 3; k++) {
            int idx = t + k * PAIR_THREADS;
            if (idx < A3_F4) cpasync16(sa + idx * 16, A + idx);
            else if (idx < B30_F4) cpasync16(sa + idx * 16, B0 + (idx - A3_F4));
            else if (idx < B31_F4 && two) cpasync16(sa + idx * 16, B0 + (idx - A3_F4));
        }
    }
}

// ---------------- epilogue for one packed s-pair ----------------
__device__ __forceinline__ void finish(ull s, int ibase, int j, bool diag, float& val) {
    float lo, hi;
    f2unpack(s, lo, hi);
    lo = fmaxf(lo, 0.f);
    hi = fmaxf(hi, 0.f);
    if ((!diag || ibase > j) && lo < 1.f) val += 1.f - sqrtf(lo);
    if ((!diag || ibase + 1 > j) && hi < 1.f) val += 1.f - sqrtf(hi);
}

// ---------------- compute: D5 single tile ----------------
__device__ __forceinline__ void compute5(unsigned jd, const float* s, int t, float& val) {
    const int ti = (jd >> 8) & 255, tj = jd & 255;
    const int w = t >> 5, l = t & 31;
    const int j = tj * TS + l;
    const bool diag = (ti == tj);
    const ulonglong2* Ap0 = (const ulonglong2*)(s + (2 * w) * P1_REC);
    const ulonglong2* Ap1 = (const ulonglong2*)(s + (2 * w + 1) * P1_REC);
    const ulonglong2* Zp  = (const ulonglong2*)(s + 4 * A5_F4 + l * Q1_STR);

    ull xa = f2dup((float)D1), xb = 0ULL, ya = f2dup((float)D1), yb = 0ULL;
#pragma unroll
    for (int qq = 0; qq < L1 / 2; qq++) {
        ulonglong2 z = Zp[qq];
        ulonglong2 a0 = Ap0[qq];
        ulonglong2 a1 = Ap1[qq];
        xa = fma2(a0.x, z.x, xa);
        xb = fma2(a0.y, z.y, xb);
        ya = fma2(a1.x, z.x, ya);
        yb = fma2(a1.y, z.y, yb);
    }
    const int ib = ti * TS + 4 * w;
    finish(add2(xa, xb), ib, j, diag, val);
    finish(add2(ya, yb), ib + 2, j, diag, val);
}

// ---------------- compute: D3 double tile (A loads shared in registers) ----------------
__device__ __forceinline__ void compute3x2(unsigned jd, const float* s, int t, float& val) {
    const int ti = (jd >> 8) & 255, tjp = jd & 255;
    const int tj0 = 2 * tjp;
    const bool two = (tj0 + 1 <= ti);
    const int w = t >> 5, l = t & 31;
    const ulonglong2* Ap0 = (const ulonglong2*)(s + (2 * w) * P0_REC);
    const ulonglong2* Ap1 = (const ulonglong2*)(s + (2 * w + 1) * P0_REC);
    const ulonglong2* Z0  = (const ulonglong2*)(s + 4 * A3_F4 + l * Q0_STR);
    const ulonglong2* Z1  = (const ulonglong2*)(s + 4 * A3_F4 + TS * Q0_STR + l * Q0_STR);

    ull x0a = f2dup((float)D0), x0b = 0ULL, y0a = f2dup((float)D0), y0b = 0ULL;
    ull x1a = x0a, x1b = 0ULL, y1a = x0a, y1b = 0ULL;
    if (two) {
#pragma unroll
        for (int qq = 0; qq < L0 / 2; qq++) {
            ulonglong2 a0 = Ap0[qq];
            ulonglong2 a1 = Ap1[qq];
            ulonglong2 z0 = Z0[qq];
            ulonglong2 z1 = Z1[qq];
            x0a = fma2(a0.x, z0.x, x0a);
            x0b = fma2(a0.y, z0.y, x0b);
            y0a = fma2(a1.x, z0.x, y0a);
            y0b = fma2(a1.y, z0.y, y0b);
            x1a = fma2(a0.x, z1.x, x1a);
            x1b = fma2(a0.y, z1.y, x1b);
            y1a = fma2(a1.x, z1.x, y1a);
            y1b = fma2(a1.y, z1.y, y1b);
        }
    } else {
#pragma unroll
        for (int qq = 0; qq < L0 / 2; qq++) {
            ulonglong2 a0 = Ap0[qq];
            ulonglong2 a1 = Ap1[qq];
            ulonglong2 z0 = Z0[qq];
            x0a = fma2(a0.x, z0.x, x0a);
            x0b = fma2(a0.y, z0.y, x0b);
            y0a = fma2(a1.x, z0.x, y0a);
            y0b = fma2(a1.y, z0.y, y0b);
        }
    }
    const int ib = ti * TS + 4 * w;
    {
        const int j = tj0 * TS + l;
        const bool diag = (ti == tj0);
        finish(add2(x0a, x0b), ib, j, diag, val);
        finish(add2(y0a, y0b), ib + 2, j, diag, val);
    }
    if (two) {
        const int j = (tj0 + 1) * TS + l;
        const bool diag = (ti == tj0 + 1);
        finish(add2(x1a, x1b), ib, j, diag, val);
        finish(add2(y1a, y1b), ib + 2, j, diag, val);
    }
}

// ---------------- Single fused persistent kernel ----------------
__global__ void __launch_bounds__(PAIR_THREADS, 4) fused_kernel(
    float* __restrict__ out, const float* __restrict__ k0, const float* __restrict__ k1) {
    __shared__ __align__(16) float sbuf[2][SBUF];
    __shared__ float warp_sums[2][PAIR_THREADS / 32];
    __shared__ int s_next;

    const int t = threadIdx.x;
    const int b = blockIdx.x;
    const int w = t >> 5;
    const int l = t & 31;

    // ======== Phase A: one HALF-task per warp (lane 0), register-lean ========
    {
        if (b == 0 && t == 0) {
            g_sum0 = 0.0;
            g_sum1 = 0.0;
            g_next = GRID_PAIR;
        }
        if (l == 0) {
            int gw = b * 8 + w;  // global warp id, [0, 4736)
            if (gw < 2 * N1) {
                // D5 half-tasks: matrix gw>>1; even -> p-side (GJ), odd -> q-side
                if (gw & 1) prep5_q(gw >> 1, k1);
                else        prep5_p(gw >> 1, k1);
            } else if (gw < 2 * N1 + N0) {
                prep0_all(gw - 2 * N1, k0);
            }
        }
        // job table: jid = b*3 + t for t<3 (592*3 = 1776 >= NJOB)
        if (t < 3) {
            int jid = b * 3 + t;
            if (jid < NJOB) {
                if (jid < NJOB5) {
                    int ti, tj;
                    tri_decode(jid, ti, tj);
                    g_job[jid] = 0x80000000u | ((unsigned)ti << 8) | (unsigned)tj;
                } else {
                    int jj = jid - NJOB5;
                    int ti = 0, acc = 0;
                    while (acc + (ti / 2 + 1) <= jj) { acc += ti / 2 + 1; ti++; }
                    g_job[jid] = ((unsigned)ti << 8) | (unsigned)(jj - acc);
                }
            }
        }
        __syncthreads();
        // grid-wide barrier (all 592 blocks resident: grid == one full wave)
        if (t == 0) {
            __threadfence();
            atomicAdd(&g_arrive, 1u);
            while (*(volatile unsigned int*)&g_arrive < GRID_PAIR) {}
        }
        __syncthreads();
    }

    // ======== Phase B: pairwise loss (R11 pipeline, verbatim) ========
    float val0 = 0.f, val1 = 0.f;

    unsigned jd_curr = __ldcg(&g_job[b]);
    issue_copies(jd_curr, sbuf[0], t);
    asm volatile("cp.async.commit_group;" ::: "memory");
    if (t == 0) s_next = atomicAdd(&g_next, 1);
    asm volatile("cp.async.wait_group 0;" ::: "memory");
    __syncthreads();
    int nxt = s_next;
    int buf = 0;

    while (true) {
        unsigned jd_next = 0;
        if (nxt < NJOB) {
            jd_next = __ldcg(&g_job[nxt]);
            issue_copies(jd_next, sbuf[buf ^ 1], t);
            if (t == 0) s_next = atomicAdd(&g_next, 1);
        }
        asm volatile("cp.async.commit_group;" ::: "memory");
        if (jd_curr & 0x80000000u) compute5(jd_curr, sbuf[buf], t, val1);
        else                       compute3x2(jd_curr, sbuf[buf], t, val0);
        if (nxt >= NJOB) break;
        asm volatile("cp.async.wait_group 0;" ::: "memory");
        __syncthreads();
        jd_curr = jd_next;
        nxt = s_next;
        buf ^= 1;
    }

    // block reduction of both accumulators
#pragma unroll
    for (int off = 16; off > 0; off >>= 1) {
        val0 += __shfl_down_sync(0xFFFFFFFFu, val0, off);
        val1 += __shfl_down_sync(0xFFFFFFFFu, val1, off);
    }
    if (l == 0) {
        warp_sums[0][w] = val0;
        warp_sums[1][w] = val1;
    }
    __syncthreads();
    if (t == 0) {
        float b0 = 0.f, b1 = 0.f;
#pragma unroll
        for (int ww = 0; ww < PAIR_THREADS / 32; ww++) {
            b0 += warp_sums[0][ww];
            b1 += warp_sums[1][ww];
        }
        if (b0 != 0.f) atomicAdd(&g_sum0, (double)b0);
        if (b1 != 0.f) atomicAdd(&g_sum1, (double)b1);
        __threadfence();
        unsigned int done = atomicAdd(&g_done, 1u);
        if (done == GRID_PAIR - 1) {
            __threadfence();
            double s0 = *(volatile double*)&g_sum0;
            double s1 = *(volatile double*)&g_sum1;
            double l0 = 2.0 * s0 / ((double)N0 * (double)(N0 - 1));
            double l1 = 2.0 * s1 / ((double)N1 * (double)(N1 - 1));
            out[0] = (float)(0.5 * (l0 + l1));
            g_done = 0;    // reset for next graph replay
            g_arrive = 0;  // reset phase-A barrier
        }
    }
}

extern "C" void kernel_launch(void* const* d_in, const int* in_sizes, int n_in,
                              void* d_out, int out_size) {
    const float* k0 = (const float*)d_in[0];
    const float* k1 = (const float*)d_in[1];
    float* out = (float*)d_out;

    fused_kernel<<<GRID_PAIR, PAIR_THREADS>>>(out, k0, k1);
}